// round 3
// baseline (speedup 1.0000x reference)
#include <cuda_runtime.h>
#include <cstdint>

#define BSZ 2
#define NN  4096
#define JJ  3
#define CC  32
#define KO  32
#define MJ  (NN*JJ)               // 12288
#define BM  128
#define BKT 32
#define SPLITS 16
#define ITERS ((MJ/BKT)/SPLITS)   // 24
#define WS  36                    // padded smem stride: (4*lg+lt)%32 conflict-free
#define STAGES 2

__device__ float g_t[BSZ * MJ * KO];                // t[b][mj][k] (tf32-rounded bits)
__device__ float g_part[SPLITS * BSZ * KO * NN];    // split-K partials (16 MB)

__device__ __forceinline__ uint32_t f2tf32(float f) {
    uint32_t o;
    asm("cvt.rna.tf32.f32 %0, %1;" : "=r"(o) : "f"(f));
    return o;
}

// ---------------------------------------------------------------------------
// t[b][m*3+j][k] = (1+2^-11) * sum_c conv_w[k][j*CC+c] * x[b][m][c]
// The (1+2^-11) factor cancels the expected truncation bias of feeding raw
// fp32 W bits to tf32 MMA (HW truncates the low 13 mantissa bits).
// ---------------------------------------------------------------------------
__global__ void precompute_t_kernel(const float* __restrict__ x,
                                    const float* __restrict__ cw) {
    int tid = blockIdx.x * blockDim.x + threadIdx.x;   // exact grid
    int k  = tid & 31;
    int j  = (tid >> 5) % 3;
    int bm = tid / 96;
    const float* xr = x  + (size_t)bm * CC;
    const float* wr = cw + k * (JJ * CC) + j * CC;
    float s = 0.f;
#pragma unroll
    for (int c = 0; c < CC; ++c) s = fmaf(wr[c], xr[c], s);
    s *= (1.0f + 4.8828125e-4f);                       // 1 + 2^-11
    ((uint32_t*)g_t)[tid] = f2tf32(s);
}

// ---------------------------------------------------------------------------
// Split-K tf32 GEMM with cp.async double buffering.
// part[sp][b][k][n] = sum_{kk slice} W[b][n][kk] * t[b][kk][k]
// ---------------------------------------------------------------------------
__global__ __launch_bounds__(256, 4) void gemm_kernel(const float* __restrict__ W) {
    __shared__ uint32_t Wsh[STAGES][BM * WS];    // A tiles, raw fp32 bits
    __shared__ uint32_t Tsh[STAGES][BKT * WS];   // B tiles [kk][ko], tf32 bits

    const int b   = blockIdx.z;
    const int n0  = blockIdx.x * BM;
    const int sp  = blockIdx.y;
    const int kk0 = sp * (ITERS * BKT);

    const int tid  = threadIdx.x;
    const int warp = tid >> 5, lane = tid & 31;
    const int lg   = lane >> 2, lt = lane & 3;
    const int row0 = warp * 16;

    const float* Wbase = W   + ((size_t)(b * NN + n0)) * MJ + kk0;
    const float* Tbase = g_t + ((size_t)b * MJ + kk0) * KO;

    const int wlr = tid >> 3;              // W tile: 4 rows/thread (+q*32)
    const int wlc = (tid & 7) * 4;
    const int tkk = tid >> 3;              // t tile: 1 float4/thread
    const int tko = (tid & 7) * 4;

    float acc[4][4];
#pragma unroll
    for (int i = 0; i < 4; ++i)
#pragma unroll
        for (int j = 0; j < 4; ++j) acc[i][j] = 0.f;

#define ISSUE_TILE(s, t)                                                          \
    {                                                                             \
        const float* wp_ = Wbase + (t) * BKT;                                     \
        _Pragma("unroll")                                                         \
        for (int q = 0; q < 4; ++q) {                                             \
            uint32_t d_ = (uint32_t)__cvta_generic_to_shared(                     \
                &Wsh[s][(wlr + q * 32) * WS + wlc]);                              \
            asm volatile("cp.async.cg.shared.global [%0], [%1], 16;" ::           \
                         "r"(d_), "l"(wp_ + (size_t)(wlr + q * 32) * MJ + wlc));  \
        }                                                                         \
        uint32_t dt_ = (uint32_t)__cvta_generic_to_shared(                        \
            &Tsh[s][tkk * WS + tko]);                                             \
        asm volatile("cp.async.cg.shared.global [%0], [%1], 16;" ::               \
                     "r"(dt_), "l"(Tbase + (t) * (BKT * KO) + tid * 4));          \
    }

    ISSUE_TILE(0, 0);
    asm volatile("cp.async.commit_group;");

    for (int it = 0; it < ITERS; ++it) {
        asm volatile("cp.async.wait_group 0;");
        __syncthreads();                      // tile it visible; compute(it-1) done
        if (it + 1 < ITERS) ISSUE_TILE((it + 1) & 1, it + 1);
        asm volatile("cp.async.commit_group;");

        const uint32_t* Ws = Wsh[it & 1];
        const uint32_t* Ts = Tsh[it & 1];
#pragma unroll
        for (int s4 = 0; s4 < 4; ++s4) {
            const int kc = s4 * 8;
            uint32_t a0 = Ws[(row0 + lg)     * WS + kc + lt];
            uint32_t a1 = Ws[(row0 + lg + 8) * WS + kc + lt];
            uint32_t a2 = Ws[(row0 + lg)     * WS + kc + lt + 4];
            uint32_t a3 = Ws[(row0 + lg + 8) * WS + kc + lt + 4];
#pragma unroll
            for (int nt = 0; nt < 4; ++nt) {
                uint32_t b0 = Ts[(kc + lt)     * WS + nt * 8 + lg];
                uint32_t b1 = Ts[(kc + lt + 4) * WS + nt * 8 + lg];
                asm volatile(
                    "mma.sync.aligned.m16n8k8.row.col.f32.tf32.tf32.f32 "
                    "{%0,%1,%2,%3}, {%4,%5,%6,%7}, {%8,%9}, {%0,%1,%2,%3};"
                    : "+f"(acc[nt][0]), "+f"(acc[nt][1]),
                      "+f"(acc[nt][2]), "+f"(acc[nt][3])
                    : "r"(a0), "r"(a1), "r"(a2), "r"(a3), "r"(b0), "r"(b1));
            }
        }
    }
#undef ISSUE_TILE

    // ---- epilogue: stage tile in smem, coalesced STG to partial buffer ----
    __syncthreads();
    float* stg = (float*)&Wsh[0][0];                  // 128*33*4 <= 128*36*4
#pragma unroll
    for (int nt = 0; nt < 4; ++nt) {
        int col = nt * 8 + lt * 2;
        stg[(row0 + lg)     * 33 + col]     = acc[nt][0];
        stg[(row0 + lg)     * 33 + col + 1] = acc[nt][1];
        stg[(row0 + lg + 8) * 33 + col]     = acc[nt][2];
        stg[(row0 + lg + 8) * 33 + col + 1] = acc[nt][3];
    }
    __syncthreads();
    float* pbase = g_part + ((size_t)sp * BSZ + b) * (KO * NN);
#pragma unroll
    for (int p = 0; p < 16; ++p) {
        int idx = p * 256 + tid;               // 4096 outputs
        int nl = idx & 127, k = idx >> 7;
        pbase[(size_t)k * NN + n0 + nl] = stg[nl * 33 + k];
    }
}

// ---------------------------------------------------------------------------
// out[b][k][n] = bias[k] + sum_sp part[sp][b][k][n]
// ---------------------------------------------------------------------------
__global__ void reduce_kernel(float* __restrict__ out, const float* __restrict__ cb) {
    int i = blockIdx.x * blockDim.x + threadIdx.x;    // 262144 exact
    float s = cb[(i >> 12) & 31];
#pragma unroll
    for (int sp = 0; sp < SPLITS; ++sp)
        s += g_part[(size_t)sp * (BSZ * KO * NN) + i];
    out[i] = s;
}

// ---------------------------------------------------------------------------
extern "C" void kernel_launch(void* const* d_in, const int* in_sizes, int n_in,
                              void* d_out, int out_size) {
    const float* W  = (const float*)d_in[0];
    const float* x  = (const float*)d_in[1];
    const float* cw = (const float*)d_in[2];
    const float* cb = (const float*)d_in[3];
    float* out = (float*)d_out;

    precompute_t_kernel<<<(BSZ * MJ * KO) / 256, 256>>>(x, cw);

    dim3 grid(NN / BM, SPLITS, BSZ);
    gemm_kernel<<<grid, 256>>>(W);

    reduce_kernel<<<(BSZ * KO * NN) / 256, 256>>>(out, cb);
}

// round 4
// speedup vs baseline: 1.7979x; 1.7979x over previous
#include <cuda_runtime.h>
#include <cstdint>

#define BSZ 2
#define NN  4096
#define JJ  3
#define CC  32
#define KO  32
#define MJ  (NN*JJ)               // 12288
#define BM  128
#define BKT 32
#define SPLITS 16
#define ITERS ((MJ/BKT)/SPLITS)   // 24
#define WS  36                    // padded smem stride
#define STAGES 3
#define STAGE_SZ ((BM + BKT) * WS)      // words per stage (5760 = 23040 B)
#define GEMM_SMEM (STAGES * STAGE_SZ * 4)  // 69120 B

__device__ float g_t[BSZ * MJ * KO];                // t[b][mj][k] (tf32 bits)
__device__ float g_part[SPLITS * BSZ * KO * NN];    // split-K partials (16 MB)

__device__ __forceinline__ uint32_t f2tf32(float f) {
    uint32_t o;
    asm("cvt.rna.tf32.f32 %0, %1;" : "=r"(o) : "f"(f));
    return o;
}

// ---------------------------------------------------------------------------
// t[bm][j*32+k] = (1+2^-11) * sum_c conv_w[k][j*32+c] * x[bm][c]
// smem-tiled: conv_w staged once (stride 100), x tile 32 rows (stride 36).
// Block: 256 threads, 32 bm rows, 3072 outputs (12/thread), all coalesced.
// ---------------------------------------------------------------------------
__global__ __launch_bounds__(256) void precompute_t_kernel(const float* __restrict__ x,
                                                           const float* __restrict__ cw) {
    __shared__ float cws[KO * 100];     // 32 rows x 96, stride 100 (16B aligned)
    __shared__ float xs[32 * WS];       // 32 rows x 32, stride 36

    const int tid = threadIdx.x;
    const int bm0 = blockIdx.x * 32;

    // load conv_w: 32x96 = 768 float4, 3 per thread
#pragma unroll
    for (int p = 0; p < 3; ++p) {
        int idx = p * 256 + tid;               // 0..767
        int r = idx / 24, cv = idx % 24;       // 24 float4 per row
        float4 v = ((const float4*)cw)[idx];
        *(float4*)(cws + r * 100 + cv * 4) = v;
    }
    // load x tile: 32x32 = 256 float4, 1 per thread
    {
        int r = tid >> 3, cv = tid & 7;
        float4 v = ((const float4*)(x + (size_t)bm0 * CC))[tid];
        *(float4*)(xs + r * WS + cv * 4) = v;
    }
    __syncthreads();

#pragma unroll
    for (int p = 0; p < 12; ++p) {
        int o = p * 256 + tid;                 // 0..3071
        int bm = o / 96, jk = o % 96;
        int j = jk >> 5, k = jk & 31;
        const float* xr = xs + bm * WS;
        const float* wr = cws + k * 100 + j * 32;
        float s = 0.f;
#pragma unroll
        for (int cv = 0; cv < 8; ++cv) {
            float4 xv = *(const float4*)(xr + cv * 4);
            float4 wv = *(const float4*)(wr + cv * 4);
            s = fmaf(xv.x, wv.x, s);
            s = fmaf(xv.y, wv.y, s);
            s = fmaf(xv.z, wv.z, s);
            s = fmaf(xv.w, wv.w, s);
        }
        s *= (1.0f + 4.8828125e-4f);           // cancel tf32 truncation bias on W
        ((uint32_t*)g_t)[(size_t)bm0 * 96 + o] = f2tf32(s);
    }
}

// ---------------------------------------------------------------------------
// Split-K tf32 GEMM, cp.async 3-stage pipeline (2 tiles in flight).
// part[sp][b][k][n] = sum_{kk slice} W[b][n][kk] * t[b][kk][k]
// ---------------------------------------------------------------------------
extern __shared__ uint32_t smem_dyn[];

__global__ __launch_bounds__(256, 3) void gemm_kernel(const float* __restrict__ W) {
    const int b   = blockIdx.z;
    const int n0  = blockIdx.x * BM;
    const int sp  = blockIdx.y;
    const int kk0 = sp * (ITERS * BKT);

    const int tid  = threadIdx.x;
    const int warp = tid >> 5, lane = tid & 31;
    const int lg   = lane >> 2, lt = lane & 3;
    const int row0 = warp * 16;

    const float* Wbase = W   + ((size_t)(b * NN + n0)) * MJ + kk0;
    const float* Tbase = g_t + ((size_t)b * MJ + kk0) * KO;

    const int wlr = tid >> 3;              // W tile: 4 rows/thread (+q*32)
    const int wlc = (tid & 7) * 4;
    const int tkk = tid >> 3;              // t tile: 1 float4/thread
    const int tko = (tid & 7) * 4;

    float acc[4][4];
#pragma unroll
    for (int i = 0; i < 4; ++i)
#pragma unroll
        for (int j = 0; j < 4; ++j) acc[i][j] = 0.f;

#define ISSUE_TILE(s, t)                                                          \
    {                                                                             \
        uint32_t* Wst = smem_dyn + (s) * STAGE_SZ;                                \
        uint32_t* Tst = Wst + BM * WS;                                            \
        const float* wp_ = Wbase + (t) * BKT;                                     \
        _Pragma("unroll")                                                         \
        for (int q = 0; q < 4; ++q) {                                             \
            uint32_t d_ = (uint32_t)__cvta_generic_to_shared(                     \
                &Wst[(wlr + q * 32) * WS + wlc]);                                 \
            asm volatile("cp.async.cg.shared.global [%0], [%1], 16;" ::           \
                         "r"(d_), "l"(wp_ + (size_t)(wlr + q * 32) * MJ + wlc));  \
        }                                                                         \
        uint32_t dt_ = (uint32_t)__cvta_generic_to_shared(                        \
            &Tst[tkk * WS + tko]);                                                \
        asm volatile("cp.async.cg.shared.global [%0], [%1], 16;" ::               \
                     "r"(dt_), "l"(Tbase + (t) * (BKT * KO) + tid * 4));          \
    }

    ISSUE_TILE(0, 0);
    asm volatile("cp.async.commit_group;");
    ISSUE_TILE(1, 1);
    asm volatile("cp.async.commit_group;");

    int s_cur = 0, s_nxt = 2;
    for (int it = 0; it < ITERS; ++it) {
        asm volatile("cp.async.wait_group 1;");   // tile it arrived (newest may pend)
        __syncthreads();                          // visible to all; compute(it-1) done
        if (it + 2 < ITERS) ISSUE_TILE(s_nxt, it + 2);
        asm volatile("cp.async.commit_group;");   // commit every iter (may be empty)

        const uint32_t* Ws = smem_dyn + s_cur * STAGE_SZ;
        const uint32_t* Ts = Ws + BM * WS;
#pragma unroll
        for (int s4 = 0; s4 < 4; ++s4) {
            const int kc = s4 * 8;
            uint32_t a0 = Ws[(row0 + lg)     * WS + kc + lt];
            uint32_t a1 = Ws[(row0 + lg + 8) * WS + kc + lt];
            uint32_t a2 = Ws[(row0 + lg)     * WS + kc + lt + 4];
            uint32_t a3 = Ws[(row0 + lg + 8) * WS + kc + lt + 4];
#pragma unroll
            for (int nt = 0; nt < 4; ++nt) {
                uint32_t b0 = Ts[(kc + lt)     * WS + nt * 8 + lg];
                uint32_t b1 = Ts[(kc + lt + 4) * WS + nt * 8 + lg];
                asm volatile(
                    "mma.sync.aligned.m16n8k8.row.col.f32.tf32.tf32.f32 "
                    "{%0,%1,%2,%3}, {%4,%5,%6,%7}, {%8,%9}, {%0,%1,%2,%3};"
                    : "+f"(acc[nt][0]), "+f"(acc[nt][1]),
                      "+f"(acc[nt][2]), "+f"(acc[nt][3])
                    : "r"(a0), "r"(a1), "r"(a2), "r"(a3), "r"(b0), "r"(b1));
            }
        }
        s_cur = (s_cur + 1) % 3;
        s_nxt = (s_nxt + 1) % 3;
    }
#undef ISSUE_TILE

    // ---- epilogue: stage tile in smem, coalesced STG to partial buffer ----
    __syncthreads();
    float* stg = (float*)smem_dyn;                    // 128*33*4 = 16.9 KB
#pragma unroll
    for (int nt = 0; nt < 4; ++nt) {
        int col = nt * 8 + lt * 2;
        stg[(row0 + lg)     * 33 + col]     = acc[nt][0];
        stg[(row0 + lg)     * 33 + col + 1] = acc[nt][1];
        stg[(row0 + lg + 8) * 33 + col]     = acc[nt][2];
        stg[(row0 + lg + 8) * 33 + col + 1] = acc[nt][3];
    }
    __syncthreads();
    float* pbase = g_part + ((size_t)sp * BSZ + b) * (KO * NN);
#pragma unroll
    for (int p = 0; p < 16; ++p) {
        int idx = p * 256 + tid;               // 4096 outputs
        int nl = idx & 127, k = idx >> 7;
        pbase[(size_t)k * NN + n0 + nl] = stg[nl * 33 + k];
    }
}

// ---------------------------------------------------------------------------
// out[b][k][n] = bias[k] + sum_sp part[sp][b][k][n]
// ---------------------------------------------------------------------------
__global__ void reduce_kernel(float* __restrict__ out, const float* __restrict__ cb) {
    int i = blockIdx.x * blockDim.x + threadIdx.x;    // 262144 exact
    float s = cb[(i >> 12) & 31];
#pragma unroll
    for (int sp = 0; sp < SPLITS; ++sp)
        s += g_part[(size_t)sp * (BSZ * KO * NN) + i];
    out[i] = s;
}

// ---------------------------------------------------------------------------
extern "C" void kernel_launch(void* const* d_in, const int* in_sizes, int n_in,
                              void* d_out, int out_size) {
    const float* W  = (const float*)d_in[0];
    const float* x  = (const float*)d_in[1];
    const float* cw = (const float*)d_in[2];
    const float* cb = (const float*)d_in[3];
    float* out = (float*)d_out;

    static int attr_set = 0;
    if (!attr_set) {
        cudaFuncSetAttribute(gemm_kernel,
                             cudaFuncAttributeMaxDynamicSharedMemorySize, GEMM_SMEM);
        attr_set = 1;
    }

    precompute_t_kernel<<<(BSZ * NN) / 32, 256>>>(x, cw);

    dim3 grid(NN / BM, SPLITS, BSZ);
    gemm_kernel<<<grid, 256, GEMM_SMEM>>>(W);

    reduce_kernel<<<(BSZ * KO * NN) / 256, 256>>>(out, cb);
}

// round 5
// speedup vs baseline: 2.0192x; 1.1231x over previous
#include <cuda_runtime.h>
#include <cstdint>

#define BSZ 2
#define NN  4096
#define JJ  3
#define CC  32
#define KO  32
#define MJ  (NN*JJ)               // 12288
#define BM  256
#define BKT 32
#define SPLITS 4
#define ITERS ((MJ/BKT)/SPLITS)   // 96
#define WS  36                    // padded smem stride (conflict-free frags)
#define STAGES 3
#define STAGE_SZ ((BM + BKT) * WS)          // 10368 words
#define GEMM_SMEM (STAGES * STAGE_SZ * 4)   // 124416 B

__device__ float g_t[BSZ * MJ * KO];                // t[b][mj][k] (tf32 bits)
__device__ float g_part[SPLITS * BSZ * KO * NN];    // split-K partials (4 MB)

__device__ __forceinline__ uint32_t f2tf32(float f) {
    uint32_t o;
    asm("cvt.rna.tf32.f32 %0, %1;" : "=r"(o) : "f"(f));
    return o;
}

// ---------------------------------------------------------------------------
// t[bm][j*32+k] = (1+2^-11) * sum_c conv_w[k][j*32+c] * x[bm][c]
// 16 bm rows per block, grid 512. All loads/stores coalesced, math from smem.
// ---------------------------------------------------------------------------
__global__ __launch_bounds__(256) void precompute_t_kernel(const float* __restrict__ x,
                                                           const float* __restrict__ cw) {
    __shared__ float cws[KO * 100];     // 32 x 96, stride 100
    __shared__ float xs[16 * WS];       // 16 x 32, stride 36

    const int tid = threadIdx.x;
    const int bm0 = blockIdx.x * 16;

#pragma unroll
    for (int p = 0; p < 3; ++p) {
        int idx = p * 256 + tid;               // 768 float4 of conv_w
        int r = idx / 24, cv = idx % 24;
        float4 v = ((const float4*)cw)[idx];
        *(float4*)(cws + r * 100 + cv * 4) = v;
    }
    if (tid < 128) {                           // 16x32 = 128 float4 of x
        int r = tid >> 3, cv = tid & 7;
        float4 v = ((const float4*)(x + (size_t)bm0 * CC))[tid];
        *(float4*)(xs + r * WS + cv * 4) = v;
    }
    __syncthreads();

#pragma unroll
    for (int p = 0; p < 6; ++p) {
        int o = p * 256 + tid;                 // 0..1535
        int bm = o / 96, jk = o % 96;
        int j = jk >> 5, k = jk & 31;
        const float* xr = xs + bm * WS;
        const float* wr = cws + k * 100 + j * 32;
        float s = 0.f;
#pragma unroll
        for (int cv = 0; cv < 8; ++cv) {
            float4 xv = *(const float4*)(xr + cv * 4);
            float4 wv = *(const float4*)(wr + cv * 4);
            s = fmaf(xv.x, wv.x, s);
            s = fmaf(xv.y, wv.y, s);
            s = fmaf(xv.z, wv.z, s);
            s = fmaf(xv.w, wv.w, s);
        }
        s *= (1.0f + 4.8828125e-4f);           // cancel tf32 truncation bias on W
        ((uint32_t*)g_t)[(size_t)bm0 * 96 + o] = f2tf32(s);
    }
}

// ---------------------------------------------------------------------------
// Split-K tf32 GEMM: BM=256 tile, 8 warps x 32 rows (2 m16 subtiles/warp,
// b-frags reused across subtiles). 3-stage cp.async ring. Single wave: 128 blocks.
// part[sp][b][k][n] = sum_{kk slice} W[b][n][kk] * t[b][kk][k]
// ---------------------------------------------------------------------------
extern __shared__ uint32_t smem_dyn[];

__global__ __launch_bounds__(256, 1) void gemm_kernel(const float* __restrict__ W) {
    const int b   = blockIdx.z;
    const int n0  = blockIdx.x * BM;
    const int sp  = blockIdx.y;
    const int kk0 = sp * (ITERS * BKT);

    const int tid  = threadIdx.x;
    const int warp = tid >> 5, lane = tid & 31;
    const int lg   = lane >> 2, lt = lane & 3;
    const int row0 = warp * 32;

    const float* Wbase = W   + ((size_t)(b * NN + n0)) * MJ + kk0;
    const float* Tbase = g_t + ((size_t)b * MJ + kk0) * KO;

    const int wlr = tid >> 3;              // W tile: 8 rows/thread (+q*32)
    const int wlc = (tid & 7) * 4;
    const int tkk = tid >> 3;              // t tile: 1 float4/thread
    const int tko = (tid & 7) * 4;

    float acc[2][4][4];
#pragma unroll
    for (int m = 0; m < 2; ++m)
#pragma unroll
        for (int i = 0; i < 4; ++i)
#pragma unroll
            for (int j = 0; j < 4; ++j) acc[m][i][j] = 0.f;

#define ISSUE_TILE(s, t)                                                          \
    {                                                                             \
        uint32_t* Wst = smem_dyn + (s) * STAGE_SZ;                                \
        uint32_t* Tst = Wst + BM * WS;                                            \
        const float* wp_ = Wbase + (t) * BKT;                                     \
        _Pragma("unroll")                                                         \
        for (int q = 0; q < 8; ++q) {                                             \
            uint32_t d_ = (uint32_t)__cvta_generic_to_shared(                     \
                &Wst[(wlr + q * 32) * WS + wlc]);                                 \
            asm volatile("cp.async.cg.shared.global [%0], [%1], 16;" ::           \
                         "r"(d_), "l"(wp_ + (size_t)(wlr + q * 32) * MJ + wlc));  \
        }                                                                         \
        uint32_t dt_ = (uint32_t)__cvta_generic_to_shared(                        \
            &Tst[tkk * WS + tko]);                                                \
        asm volatile("cp.async.cg.shared.global [%0], [%1], 16;" ::               \
                     "r"(dt_), "l"(Tbase + (t) * (BKT * KO) + tid * 4));          \
    }

    ISSUE_TILE(0, 0);
    asm volatile("cp.async.commit_group;");
    ISSUE_TILE(1, 1);
    asm volatile("cp.async.commit_group;");

    int s_cur = 0, s_nxt = 2;
    for (int it = 0; it < ITERS; ++it) {
        asm volatile("cp.async.wait_group 1;");   // tile it arrived
        __syncthreads();                          // visible; compute(it-1) done
        if (it + 2 < ITERS) ISSUE_TILE(s_nxt, it + 2);
        asm volatile("cp.async.commit_group;");

        const uint32_t* Ws = smem_dyn + s_cur * STAGE_SZ;
        const uint32_t* Ts = Ws + BM * WS;
#pragma unroll
        for (int s4 = 0; s4 < 4; ++s4) {
            const int kc = s4 * 8;
            uint32_t a[2][4];
#pragma unroll
            for (int m = 0; m < 2; ++m) {
                int r = row0 + m * 16 + lg;
                a[m][0] = Ws[r * WS + kc + lt];
                a[m][1] = Ws[(r + 8) * WS + kc + lt];
                a[m][2] = Ws[r * WS + kc + lt + 4];
                a[m][3] = Ws[(r + 8) * WS + kc + lt + 4];
            }
#pragma unroll
            for (int nt = 0; nt < 4; ++nt) {
                uint32_t b0 = Ts[(kc + lt)     * WS + nt * 8 + lg];
                uint32_t b1 = Ts[(kc + lt + 4) * WS + nt * 8 + lg];
#pragma unroll
                for (int m = 0; m < 2; ++m) {
                    asm volatile(
                        "mma.sync.aligned.m16n8k8.row.col.f32.tf32.tf32.f32 "
                        "{%0,%1,%2,%3}, {%4,%5,%6,%7}, {%8,%9}, {%0,%1,%2,%3};"
                        : "+f"(acc[m][nt][0]), "+f"(acc[m][nt][1]),
                          "+f"(acc[m][nt][2]), "+f"(acc[m][nt][3])
                        : "r"(a[m][0]), "r"(a[m][1]), "r"(a[m][2]), "r"(a[m][3]),
                          "r"(b0), "r"(b1));
                }
            }
        }
        s_cur = s_cur == 2 ? 0 : s_cur + 1;
        s_nxt = s_nxt == 2 ? 0 : s_nxt + 1;
    }
#undef ISSUE_TILE

    // ---- epilogue: stage 256x32 tile in smem (stride 33), coalesced STG ----
    __syncthreads();
    float* stg = (float*)smem_dyn;                    // 256*33*4 = 33.8 KB
#pragma unroll
    for (int m = 0; m < 2; ++m)
#pragma unroll
        for (int nt = 0; nt < 4; ++nt) {
            int col = nt * 8 + lt * 2;
            int r = row0 + m * 16 + lg;
            stg[r * 33 + col]           = acc[m][nt][0];
            stg[r * 33 + col + 1]       = acc[m][nt][1];
            stg[(r + 8) * 33 + col]     = acc[m][nt][2];
            stg[(r + 8) * 33 + col + 1] = acc[m][nt][3];
        }
    __syncthreads();
    float* pbase = g_part + ((size_t)sp * BSZ + b) * (KO * NN);
#pragma unroll
    for (int p = 0; p < 32; ++p) {
        int idx = p * 256 + tid;               // 8192 outputs
        int nl = idx & 255, k = idx >> 8;
        pbase[(size_t)k * NN + n0 + nl] = stg[nl * 33 + k];
    }
}

// ---------------------------------------------------------------------------
// out[b][k][n] = bias[k] + sum_sp part[sp][b][k][n]
// ---------------------------------------------------------------------------
__global__ void reduce_kernel(float* __restrict__ out, const float* __restrict__ cb) {
    int i = blockIdx.x * blockDim.x + threadIdx.x;    // 262144 exact
    float s = cb[(i >> 12) & 31];
#pragma unroll
    for (int sp = 0; sp < SPLITS; ++sp)
        s += g_part[(size_t)sp * (BSZ * KO * NN) + i];
    out[i] = s;
}

// ---------------------------------------------------------------------------
extern "C" void kernel_launch(void* const* d_in, const int* in_sizes, int n_in,
                              void* d_out, int out_size) {
    const float* W  = (const float*)d_in[0];
    const float* x  = (const float*)d_in[1];
    const float* cw = (const float*)d_in[2];
    const float* cb = (const float*)d_in[3];
    float* out = (float*)d_out;

    static int attr_set = 0;
    if (!attr_set) {
        cudaFuncSetAttribute(gemm_kernel,
                             cudaFuncAttributeMaxDynamicSharedMemorySize, GEMM_SMEM);
        attr_set = 1;
    }

    precompute_t_kernel<<<(BSZ * NN) / 16, 256>>>(x, cw);

    dim3 grid(NN / BM, SPLITS, BSZ);                  // 16 x 4 x 2 = 128 blocks
    gemm_kernel<<<grid, 256, GEMM_SMEM>>>(W);

    reduce_kernel<<<(BSZ * KO * NN) / 256, 256>>>(out, cb);
}

// round 6
// speedup vs baseline: 2.1070x; 1.0435x over previous
#include <cuda_runtime.h>
#include <cstdint>

#define BSZ 2
#define NN  4096
#define JJ  3
#define CC  32
#define KO  32
#define MJ  (NN*JJ)               // 12288
#define BM  256
#define BKT 32
#define NTILES (NN/BM)            // 16 n-tiles per batch
#define CHUNKS (MJ/BKT)           // 384 k-chunks per tile
#define TOTAL_STEPS (BSZ*NTILES*CHUNKS)   // 12288
#define NBLK 148                  // one block per SM, single wave
#define WS  36                    // padded smem stride (conflict-free frags)
#define STAGES 3
#define STAGE_SZ ((BM + BKT) * WS)          // 10368 words
#define GEMM_SMEM (STAGES * STAGE_SZ * 4)   // 124416 B

__device__ float g_t[BSZ * MJ * KO];        // t[b][mj][k] (tf32 bits)

__device__ __forceinline__ uint32_t f2tf32(float f) {
    uint32_t o;
    asm("cvt.rna.tf32.f32 %0, %1;" : "=r"(o) : "f"(f));
    return o;
}

// ---------------------------------------------------------------------------
// out[b][k][n] = bias[k]
// ---------------------------------------------------------------------------
__global__ void init_out_kernel(float* __restrict__ out, const float* __restrict__ bias) {
    int i = blockIdx.x * blockDim.x + threadIdx.x;
    if (i < BSZ * KO * NN) out[i] = bias[(i >> 12) & 31];
}

// ---------------------------------------------------------------------------
// t[bm][j*32+k] = (1+2^-11) * sum_c conv_w[k][j*32+c] * x[bm][c]
// ---------------------------------------------------------------------------
__global__ __launch_bounds__(256) void precompute_t_kernel(const float* __restrict__ x,
                                                           const float* __restrict__ cw) {
    __shared__ float cws[KO * 100];     // 32 x 96, stride 100
    __shared__ float xs[16 * WS];       // 16 x 32, stride 36

    const int tid = threadIdx.x;
    const int bm0 = blockIdx.x * 16;

#pragma unroll
    for (int p = 0; p < 3; ++p) {
        int idx = p * 256 + tid;               // 768 float4 of conv_w
        int r = idx / 24, cv = idx % 24;
        float4 v = ((const float4*)cw)[idx];
        *(float4*)(cws + r * 100 + cv * 4) = v;
    }
    if (tid < 128) {                           // 16x32 = 128 float4 of x
        int r = tid >> 3, cv = tid & 7;
        float4 v = ((const float4*)(x + (size_t)bm0 * CC))[tid];
        *(float4*)(xs + r * WS + cv * 4) = v;
    }
    __syncthreads();

#pragma unroll
    for (int p = 0; p < 6; ++p) {
        int o = p * 256 + tid;                 // 0..1535
        int bm = o / 96, jk = o % 96;
        int j = jk >> 5, k = jk & 31;
        const float* xr = xs + bm * WS;
        const float* wr = cws + k * 100 + j * 32;
        float s = 0.f;
#pragma unroll
        for (int cv = 0; cv < 8; ++cv) {
            float4 xv = *(const float4*)(xr + cv * 4);
            float4 wv = *(const float4*)(wr + cv * 4);
            s = fmaf(xv.x, wv.x, s);
            s = fmaf(xv.y, wv.y, s);
            s = fmaf(xv.z, wv.z, s);
            s = fmaf(xv.w, wv.w, s);
        }
        s *= (1.0f + 4.8828125e-4f);           // cancel tf32 truncation bias on W
        ((uint32_t*)g_t)[(size_t)bm0 * 96 + o] = f2tf32(s);
    }
}

// ---------------------------------------------------------------------------
// Balanced persistent split-K tf32 GEMM.
// Work space: 12288 chunk-steps; block i owns a contiguous ~83-step range,
// crossing at most one tile boundary (<= 2 segments). Each segment streams
// W via a 3-stage cp.async ring and flushes acc with coalesced atomicAdd.
// ---------------------------------------------------------------------------
extern __shared__ uint32_t smem_dyn[];

__global__ __launch_bounds__(256, 1) void gemm_kernel(const float* __restrict__ W,
                                                      float* __restrict__ out) {
    const int tid  = threadIdx.x;
    const int warp = tid >> 5, lane = tid & 31;
    const int lg   = lane >> 2, lt = lane & 3;
    const int row0 = warp * 32;

    const int wlr = tid >> 3;              // W tile: 8 rows/thread (+q*32)
    const int wlc = (tid & 7) * 4;
    const int tkk = tid >> 3;              // t tile: 1 float4/thread
    const int tko = (tid & 7) * 4;

    int s0 = (int)(((long long)blockIdx.x * TOTAL_STEPS) / NBLK);
    const int s_end = (int)(((long long)(blockIdx.x + 1) * TOTAL_STEPS) / NBLK);

    while (s0 < s_end) {
        const int tile = s0 / CHUNKS;
        const int seg_end = min(s_end, (tile + 1) * CHUNKS);
        const int len = seg_end - s0;
        const int b  = tile >> 4;
        const int n0 = (tile & 15) * BM;
        const int kk0 = (s0 - tile * CHUNKS) * BKT;

        const float* Wbase = W   + ((size_t)(b * NN + n0)) * MJ + kk0;
        const float* Tbase = g_t + ((size_t)b * MJ + kk0) * KO;

        float acc[2][4][4];
#pragma unroll
        for (int m = 0; m < 2; ++m)
#pragma unroll
            for (int i = 0; i < 4; ++i)
#pragma unroll
                for (int j = 0; j < 4; ++j) acc[m][i][j] = 0.f;

#define ISSUE_TILE(s, t)                                                          \
    {                                                                             \
        uint32_t* Wst = smem_dyn + (s) * STAGE_SZ;                                \
        uint32_t* Tst = Wst + BM * WS;                                            \
        const float* wp_ = Wbase + (t) * BKT;                                     \
        _Pragma("unroll")                                                         \
        for (int q = 0; q < 8; ++q) {                                             \
            uint32_t d_ = (uint32_t)__cvta_generic_to_shared(                     \
                &Wst[(wlr + q * 32) * WS + wlc]);                                 \
            asm volatile("cp.async.cg.shared.global [%0], [%1], 16;" ::           \
                         "r"(d_), "l"(wp_ + (size_t)(wlr + q * 32) * MJ + wlc));  \
        }                                                                         \
        uint32_t dt_ = (uint32_t)__cvta_generic_to_shared(                        \
            &Tst[tkk * WS + tko]);                                                \
        asm volatile("cp.async.cg.shared.global [%0], [%1], 16;" ::               \
                     "r"(dt_), "l"(Tbase + (t) * (BKT * KO) + tid * 4));          \
    }

        ISSUE_TILE(0, 0);
        asm volatile("cp.async.commit_group;");
        if (len > 1) ISSUE_TILE(1, 1);
        asm volatile("cp.async.commit_group;");

        int s_cur = 0, s_nxt = 2;
        for (int it = 0; it < len; ++it) {
            asm volatile("cp.async.wait_group 1;");   // tile it arrived
            __syncthreads();                          // visible; compute(it-1) done
            if (it + 2 < len) ISSUE_TILE(s_nxt, it + 2);
            asm volatile("cp.async.commit_group;");

            const uint32_t* Ws = smem_dyn + s_cur * STAGE_SZ;
            const uint32_t* Ts = Ws + BM * WS;
#pragma unroll
            for (int s4 = 0; s4 < 4; ++s4) {
                const int kc = s4 * 8;
                uint32_t a[2][4];
#pragma unroll
                for (int m = 0; m < 2; ++m) {
                    int r = row0 + m * 16 + lg;
                    a[m][0] = Ws[r * WS + kc + lt];
                    a[m][1] = Ws[(r + 8) * WS + kc + lt];
                    a[m][2] = Ws[r * WS + kc + lt + 4];
                    a[m][3] = Ws[(r + 8) * WS + kc + lt + 4];
                }
#pragma unroll
                for (int nt = 0; nt < 4; ++nt) {
                    uint32_t b0 = Ts[(kc + lt)     * WS + nt * 8 + lg];
                    uint32_t b1 = Ts[(kc + lt + 4) * WS + nt * 8 + lg];
#pragma unroll
                    for (int m = 0; m < 2; ++m) {
                        asm volatile(
                            "mma.sync.aligned.m16n8k8.row.col.f32.tf32.tf32.f32 "
                            "{%0,%1,%2,%3}, {%4,%5,%6,%7}, {%8,%9}, {%0,%1,%2,%3};"
                            : "+f"(acc[m][nt][0]), "+f"(acc[m][nt][1]),
                              "+f"(acc[m][nt][2]), "+f"(acc[m][nt][3])
                            : "r"(a[m][0]), "r"(a[m][1]), "r"(a[m][2]), "r"(a[m][3]),
                              "r"(b0), "r"(b1));
                    }
                }
            }
            s_cur = s_cur == 2 ? 0 : s_cur + 1;
            s_nxt = s_nxt == 2 ? 0 : s_nxt + 1;
        }
#undef ISSUE_TILE

        // ---- flush segment: stage 256x32 in smem, coalesced atomicAdd ----
        asm volatile("cp.async.wait_group 0;");
        __syncthreads();
        float* stg = (float*)smem_dyn;                // 256*33*4 = 33.8 KB
#pragma unroll
        for (int m = 0; m < 2; ++m)
#pragma unroll
            for (int nt = 0; nt < 4; ++nt) {
                int col = nt * 8 + lt * 2;
                int r = row0 + m * 16 + lg;
                stg[r * 33 + col]           = acc[m][nt][0];
                stg[r * 33 + col + 1]       = acc[m][nt][1];
                stg[(r + 8) * 33 + col]     = acc[m][nt][2];
                stg[(r + 8) * 33 + col + 1] = acc[m][nt][3];
            }
        __syncthreads();
        float* obase = out + (size_t)b * (KO * NN);
#pragma unroll
        for (int p = 0; p < 32; ++p) {
            int idx = p * 256 + tid;           // 8192 outputs
            int nl = idx & 255, k = idx >> 8;
            atomicAdd(obase + (size_t)k * NN + n0 + nl, stg[nl * 33 + k]);
        }
        __syncthreads();                        // staging reuse safe next segment

        s0 = seg_end;
    }
}

// ---------------------------------------------------------------------------
extern "C" void kernel_launch(void* const* d_in, const int* in_sizes, int n_in,
                              void* d_out, int out_size) {
    const float* W  = (const float*)d_in[0];
    const float* x  = (const float*)d_in[1];
    const float* cw = (const float*)d_in[2];
    const float* cb = (const float*)d_in[3];
    float* out = (float*)d_out;

    static int attr_set = 0;
    if (!attr_set) {
        cudaFuncSetAttribute(gemm_kernel,
                             cudaFuncAttributeMaxDynamicSharedMemorySize, GEMM_SMEM);
        attr_set = 1;
    }

    init_out_kernel<<<(BSZ * KO * NN + 255) / 256, 256>>>(out, cb);
    precompute_t_kernel<<<(BSZ * NN) / 16, 256>>>(x, cw);
    gemm_kernel<<<NBLK, 256, GEMM_SMEM>>>(W, out);
}